// round 3
// baseline (speedup 1.0000x reference)
#include <cuda_runtime.h>
#include <cstdint>

// Problem constants
static constexpr int Nb = 4, C = 12, GD = 8, GH = 16, GW = 16;
static constexpr int H = 1024, W = 1024;
static constexpr int HW = H * W;
static constexpr int GRID_PER_N = C * GD * GH * GW;       // 24576 floats
static constexpr int SMEM_FLOATS = GD * GH * GW * C;      // 24576 floats = 96KB
static constexpr int ROWS_PER_BLOCK = 8;
static constexpr int THREADS = 256;

__device__ __forceinline__ unsigned long long fma2(unsigned long long a,
                                                   unsigned long long b,
                                                   unsigned long long c) {
    unsigned long long d;
    asm("fma.rn.f32x2 %0, %1, %2, %3;" : "=l"(d) : "l"(a), "l"(b), "l"(c));
    return d;
}

__device__ __forceinline__ unsigned long long pack2(float w) {
    unsigned long long d;
    unsigned u = __float_as_uint(w);
    asm("mov.b64 %0, {%1, %1};" : "=l"(d) : "r"(u));
    return d;
}

__global__ __launch_bounds__(THREADS, 2)
void slice_kernel(const float* __restrict__ grid,
                  const float* __restrict__ guide,
                  float* __restrict__ out) {
    extern __shared__ float s[];  // [z][y][x][c] layout, 24576 floats

    const int n   = blockIdx.y;
    const int tid = threadIdx.x;

    // ---- Load + transpose grid[n] : (c,z,y,x) -> smem (z,y,x,c) ----
    const float* g = grid + (size_t)n * GRID_PER_N;
    #pragma unroll
    for (int i = tid * 4; i < GRID_PER_N; i += THREADS * 4) {
        float4 v = *reinterpret_cast<const float4*>(g + i);
        int c   = i >> 11;        // / (GD*GH*GW) = /2048
        int zyx = i & 2047;       // z*256 + y*16 + x  (x0 multiple of 4)
        int base = zyx * 12 + c;
        s[base]      = v.x;
        s[base + 12] = v.y;
        s[base + 24] = v.z;
        s[base + 36] = v.w;
    }
    __syncthreads();

    const int x0 = tid * 4;

    // x-direction weights/indices (constant across rows for this thread)
    float txv[4]; int ix0a[4], ix1a[4]; float bxa[4];
    #pragma unroll
    for (int p = 0; p < 4; ++p) {
        int x = x0 + p;
        float tx = (x + 0.5f) * (1.0f / 64.0f) - 0.5f;   // xs - 0.5
        float fx = floorf(tx);
        bxa[p] = tx - fx;
        int ifx = (int)fx;
        ix0a[p] = min(max(ifx, 0), GW - 1);
        ix1a[p] = min(max(ifx + 1, 0), GW - 1);
        txv[p] = tx; (void)txv;
    }

    #pragma unroll 1
    for (int j = 0; j < ROWS_PER_BLOCK; ++j) {
        const int row = blockIdx.x * ROWS_PER_BLOCK + j;

        // y weights
        float ty = (row + 0.5f) * (16.0f / 1024.0f) - 0.5f;
        float fy = floorf(ty);
        float by = ty - fy;
        int ify = (int)fy;
        int iy0 = min(max(ify, 0), GH - 1);
        int iy1 = min(max(ify + 1, 0), GH - 1);

        float4 gv = *reinterpret_cast<const float4*>(
            guide + (size_t)n * HW + (size_t)row * W + x0);
        float gz4[4] = {gv.x, gv.y, gv.z, gv.w};

        unsigned long long acc[4][6];
        #pragma unroll
        for (int p = 0; p < 4; ++p)
            #pragma unroll
            for (int q = 0; q < 6; ++q) acc[p][q] = 0ULL;

        #pragma unroll
        for (int p = 0; p < 4; ++p) {
            // z weights from guide
            float tz = gz4[p] * 8.0f - 0.5f;
            float fz = floorf(tz);
            float bz = tz - fz;
            int ifz = (int)fz;
            int iz0 = min(max(ifz, 0), GD - 1);
            int iz1 = min(max(ifz + 1, 0), GD - 1);

            const float bx = bxa[p];
            const int ix0 = ix0a[p], ix1 = ix1a[p];

            #pragma unroll
            for (int dz = 0; dz < 2; ++dz) {
                int zoff   = (dz ? iz1 : iz0) * (GH * GW);
                float wz   = dz ? bz : 1.0f - bz;
                #pragma unroll
                for (int dy = 0; dy < 2; ++dy) {
                    int zyoff  = zoff + (dy ? iy1 : iy0) * GW;
                    float wzy  = wz * (dy ? by : 1.0f - by);
                    #pragma unroll
                    for (int dx = 0; dx < 2; ++dx) {
                        float w = wzy * (dx ? bx : 1.0f - bx);
                        const float* cp = s + (zyoff + (dx ? ix1 : ix0)) * 12;
                        unsigned long long wp = pack2(w);
                        const ulonglong2* q2 =
                            reinterpret_cast<const ulonglong2*>(cp);
                        ulonglong2 q0 = q2[0], q1 = q2[1], qq = q2[2];
                        acc[p][0] = fma2(wp, q0.x, acc[p][0]);
                        acc[p][1] = fma2(wp, q0.y, acc[p][1]);
                        acc[p][2] = fma2(wp, q1.x, acc[p][2]);
                        acc[p][3] = fma2(wp, q1.y, acc[p][3]);
                        acc[p][4] = fma2(wp, qq.x, acc[p][4]);
                        acc[p][5] = fma2(wp, qq.y, acc[p][5]);
                    }
                }
            }
        }

        // ---- Store: per channel-pair, build float4 over the 4 pixels ----
        float* ob_base = out + (size_t)n * C * HW + (size_t)row * W + x0;
        #pragma unroll
        for (int c2 = 0; c2 < 6; ++c2) {
            float4 lo, hi;
            lo.x = __uint_as_float((unsigned)acc[0][c2]);
            lo.y = __uint_as_float((unsigned)acc[1][c2]);
            lo.z = __uint_as_float((unsigned)acc[2][c2]);
            lo.w = __uint_as_float((unsigned)acc[3][c2]);
            hi.x = __uint_as_float((unsigned)(acc[0][c2] >> 32));
            hi.y = __uint_as_float((unsigned)(acc[1][c2] >> 32));
            hi.z = __uint_as_float((unsigned)(acc[2][c2] >> 32));
            hi.w = __uint_as_float((unsigned)(acc[3][c2] >> 32));
            float* ob = ob_base + (size_t)(2 * c2) * HW;
            *reinterpret_cast<float4*>(ob)      = lo;
            *reinterpret_cast<float4*>(ob + HW) = hi;
        }
    }
}

extern "C" void kernel_launch(void* const* d_in, const int* in_sizes, int n_in,
                              void* d_out, int out_size) {
    const float* grid  = (const float*)d_in[0];   // (4,12,8,16,16) f32
    const float* guide = (const float*)d_in[1];   // (4,1,1024,1024) f32
    float* out = (float*)d_out;                   // (4,12,1024,1024) f32

    const int smem_bytes = SMEM_FLOATS * sizeof(float);  // 98304
    cudaFuncSetAttribute(slice_kernel,
                         cudaFuncAttributeMaxDynamicSharedMemorySize,
                         smem_bytes);

    dim3 gridDim(H / ROWS_PER_BLOCK, Nb);  // (128, 4)
    slice_kernel<<<gridDim, THREADS, smem_bytes>>>(grid, guide, out);
}

// round 4
// speedup vs baseline: 1.8053x; 1.8053x over previous
#include <cuda_runtime.h>
#include <cstdint>

// Problem constants
static constexpr int Nb = 4, C = 12, GD = 8, GH = 16, GW = 16;
static constexpr int H = 1024, W = 1024;
static constexpr int HW = H * W;
static constexpr int GRID_PER_N = C * GD * GH * GW;       // 24576 floats
// z-slab stride padded: 16*16*12 = 3072 -> 3076 (3076 mod 32 = 4, so the 8
// z levels occupy 8 disjoint 4-bank groups => conflict-free LDS.128 across z)
static constexpr int ZSTRIDE = GH * GW * C + 4;           // 3076 floats
static constexpr int SMEM_FLOATS = GD * ZSTRIDE;          // 24608 floats = 98432B
static constexpr int ROWS_PER_BLOCK = 2;
static constexpr int THREADS = 256;

__device__ __forceinline__ unsigned long long fma2(unsigned long long a,
                                                   unsigned long long b,
                                                   unsigned long long c) {
    unsigned long long d;
    asm("fma.rn.f32x2 %0, %1, %2, %3;" : "=l"(d) : "l"(a), "l"(b), "l"(c));
    return d;
}

__device__ __forceinline__ unsigned long long pack2(float w) {
    unsigned long long d;
    unsigned u = __float_as_uint(w);
    asm("mov.b64 %0, {%1, %1};" : "=l"(d) : "r"(u));
    return d;
}

__global__ __launch_bounds__(THREADS, 2)
void slice_kernel(const float* __restrict__ grid,
                  const float* __restrict__ guide,
                  float* __restrict__ out) {
    extern __shared__ float s[];  // [z][y*x][c] with padded z stride

    const int n   = blockIdx.y;
    const int tid = threadIdx.x;

    // ---- Load + transpose grid[n] : (c,z,y,x) -> smem (z, y*16+x, c) ----
    const float* g = grid + (size_t)n * GRID_PER_N;
    #pragma unroll
    for (int i = tid * 4; i < GRID_PER_N; i += THREADS * 4) {
        float4 v = *reinterpret_cast<const float4*>(g + i);
        int c   = i >> 11;        // / (GD*GH*GW)
        int zyx = i & 2047;       // z*256 + y*16 + x  (x multiple of 4)
        int z   = zyx >> 8;
        int yx  = zyx & 255;
        int base = z * ZSTRIDE + yx * C + c;
        s[base]          = v.x;
        s[base + C]      = v.y;
        s[base + 2 * C]  = v.z;
        s[base + 3 * C]  = v.w;
    }
    __syncthreads();

    const int x0 = tid * 4;

    // x-direction weights/indices (constant for this thread; no intra-thread
    // cell crossing since cell boundaries are at x == 32 mod 64)
    float tx = (x0 + 0.5f) * (1.0f / 64.0f) - 0.5f;
    float fx = floorf(tx);
    float bx = tx - fx;          // same fractional for all 4 px? No: differs!
    // bx differs per pixel (tx step = 1/64), but ix is shared. Keep per-pixel bx.
    int ifx = (int)fx;
    const int ix0 = min(max(ifx, 0), GW - 1);
    const int ix1 = min(max(ifx + 1, 0), GW - 1);
    float bxa[4];
    #pragma unroll
    for (int p = 0; p < 4; ++p) {
        float txp = (x0 + p + 0.5f) * (1.0f / 64.0f) - 0.5f;
        bxa[p] = txp - fx;       // fx identical for the 4 pixels
    }

    #pragma unroll 1
    for (int j = 0; j < ROWS_PER_BLOCK; ++j) {
        const int row = blockIdx.x * ROWS_PER_BLOCK + j;

        // y weights
        float ty = (row + 0.5f) * (16.0f / 1024.0f) - 0.5f;
        float fy = floorf(ty);
        float by = ty - fy;
        int ify = (int)fy;
        int iy0 = min(max(ify, 0), GH - 1);
        int iy1 = min(max(ify + 1, 0), GH - 1);

        float4 gv = *reinterpret_cast<const float4*>(
            guide + (size_t)n * HW + (size_t)row * W + x0);
        float gz4[4] = {gv.x, gv.y, gv.z, gv.w};

        unsigned long long acc[4][6];
        #pragma unroll
        for (int p = 0; p < 4; ++p)
            #pragma unroll
            for (int q = 0; q < 6; ++q) acc[p][q] = 0ULL;

        #pragma unroll
        for (int p = 0; p < 4; ++p) {
            // z weights from guide
            float tz = gz4[p] * 8.0f - 0.5f;
            float fz = floorf(tz);
            float bz = tz - fz;
            int ifz = (int)fz;
            int iz0 = min(max(ifz, 0), GD - 1);
            int iz1 = min(max(ifz + 1, 0), GD - 1);

            const float bx_p = bxa[p];

            #pragma unroll
            for (int dz = 0; dz < 2; ++dz) {
                int zoff   = (dz ? iz1 : iz0) * ZSTRIDE;
                float wz   = dz ? bz : 1.0f - bz;
                #pragma unroll
                for (int dy = 0; dy < 2; ++dy) {
                    int zyoff  = zoff + (dy ? iy1 : iy0) * (GW * C);
                    float wzy  = wz * (dy ? by : 1.0f - by);
                    #pragma unroll
                    for (int dx = 0; dx < 2; ++dx) {
                        float w = wzy * (dx ? bx_p : 1.0f - bx_p);
                        const float* cp = s + zyoff + (dx ? ix1 : ix0) * C;
                        unsigned long long wp = pack2(w);
                        const ulonglong2* q2 =
                            reinterpret_cast<const ulonglong2*>(cp);
                        ulonglong2 q0 = q2[0], q1 = q2[1], qq = q2[2];
                        acc[p][0] = fma2(wp, q0.x, acc[p][0]);
                        acc[p][1] = fma2(wp, q0.y, acc[p][1]);
                        acc[p][2] = fma2(wp, q1.x, acc[p][2]);
                        acc[p][3] = fma2(wp, q1.y, acc[p][3]);
                        acc[p][4] = fma2(wp, qq.x, acc[p][4]);
                        acc[p][5] = fma2(wp, qq.y, acc[p][5]);
                    }
                }
            }
        }

        // ---- Store: per channel-pair, build float4 over the 4 pixels ----
        float* ob_base = out + (size_t)n * C * HW + (size_t)row * W + x0;
        #pragma unroll
        for (int c2 = 0; c2 < 6; ++c2) {
            float4 lo, hi;
            lo.x = __uint_as_float((unsigned)acc[0][c2]);
            lo.y = __uint_as_float((unsigned)acc[1][c2]);
            lo.z = __uint_as_float((unsigned)acc[2][c2]);
            lo.w = __uint_as_float((unsigned)acc[3][c2]);
            hi.x = __uint_as_float((unsigned)(acc[0][c2] >> 32));
            hi.y = __uint_as_float((unsigned)(acc[1][c2] >> 32));
            hi.z = __uint_as_float((unsigned)(acc[2][c2] >> 32));
            hi.w = __uint_as_float((unsigned)(acc[3][c2] >> 32));
            float* ob = ob_base + (size_t)(2 * c2) * HW;
            *reinterpret_cast<float4*>(ob)      = lo;
            *reinterpret_cast<float4*>(ob + HW) = hi;
        }
    }
}

extern "C" void kernel_launch(void* const* d_in, const int* in_sizes, int n_in,
                              void* d_out, int out_size) {
    const float* grid  = (const float*)d_in[0];   // (4,12,8,16,16) f32
    const float* guide = (const float*)d_in[1];   // (4,1,1024,1024) f32
    float* out = (float*)d_out;                   // (4,12,1024,1024) f32

    const int smem_bytes = SMEM_FLOATS * sizeof(float);  // 98432
    cudaFuncSetAttribute(slice_kernel,
                         cudaFuncAttributeMaxDynamicSharedMemorySize,
                         smem_bytes);

    dim3 gridDim(H / ROWS_PER_BLOCK, Nb);  // (512, 4) = 2048 blocks
    slice_kernel<<<gridDim, THREADS, smem_bytes>>>(grid, guide, out);
}

// round 5
// speedup vs baseline: 2.9936x; 1.6583x over previous
#include <cuda_runtime.h>
#include <cstdint>

// Problem constants
static constexpr int Nb = 4, C = 12, GD = 8, GH = 16, GW = 16;
static constexpr int H = 1024, W = 1024;
static constexpr int HW = H * W;
static constexpr int GRID_PER_N = C * GD * GH * GW;       // 24576 floats
// z-slab stride padded: 3072 -> 3076 (mod 32 = 4): the 8 z levels occupy
// 8 disjoint 4-bank groups => conflict-free LDS.128 across z within a phase.
static constexpr int ZSTRIDE = GH * GW * C + 4;           // 3076 floats
static constexpr int SMEM_FLOATS = GD * ZSTRIDE;          // 24608 floats = 98432B
static constexpr int ROWS_PER_BLOCK = 2;
static constexpr int THREADS = 512;                        // 2 px/thread = 1 row

__device__ __forceinline__ unsigned long long fma2(unsigned long long a,
                                                   unsigned long long b,
                                                   unsigned long long c) {
    unsigned long long d;
    asm("fma.rn.f32x2 %0, %1, %2, %3;" : "=l"(d) : "l"(a), "l"(b), "l"(c));
    return d;
}

__device__ __forceinline__ unsigned long long pack2(float w) {
    unsigned long long d;
    unsigned u = __float_as_uint(w);
    asm("mov.b64 %0, {%1, %1};" : "=l"(d) : "r"(u));
    return d;
}

__global__ __launch_bounds__(THREADS, 2)
void slice_kernel(const float* __restrict__ grid,
                  const float* __restrict__ guide,
                  float* __restrict__ out) {
    extern __shared__ float s[];  // [z][y*16+x][c], padded z stride

    const int n   = blockIdx.y;
    const int tid = threadIdx.x;

    // ---- Load + transpose grid[n] : (c,z,y,x) -> smem (z, y*16+x, c) ----
    const float* g = grid + (size_t)n * GRID_PER_N;
    #pragma unroll
    for (int i = tid * 4; i < GRID_PER_N; i += THREADS * 4) {
        float4 v = *reinterpret_cast<const float4*>(g + i);
        int c   = i >> 11;        // / (GD*GH*GW)
        int zyx = i & 2047;       // z*256 + y*16 + x  (x multiple of 4)
        int z   = zyx >> 8;
        int yx  = zyx & 255;
        int base = z * ZSTRIDE + yx * C + c;
        s[base]          = v.x;
        s[base + C]      = v.y;
        s[base + 2 * C]  = v.z;
        s[base + 3 * C]  = v.w;
    }
    __syncthreads();

    const int x0 = tid * 2;      // 2 consecutive pixels per thread

    // x cell + fractionals (fx identical within the even-aligned pair)
    float tx0 = (x0 + 0.5f) * (1.0f / 64.0f) - 0.5f;
    float fx  = floorf(tx0);
    int ifx = (int)fx;
    const int ix0 = min(max(ifx, 0), GW - 1);
    const int ix1 = min(max(ifx + 1, 0), GW - 1);
    const int xo0 = ix0 * C, xo1 = ix1 * C;
    float bxa[2];
    bxa[0] = tx0 - fx;
    bxa[1] = tx0 + (1.0f / 64.0f) - fx;

    #pragma unroll 1
    for (int j = 0; j < ROWS_PER_BLOCK; ++j) {
        const int row = blockIdx.x * ROWS_PER_BLOCK + j;

        // y weights (uniform across the block row)
        float ty = (row + 0.5f) * (16.0f / 1024.0f) - 0.5f;
        float fy = floorf(ty);
        float by = ty - fy;
        int ify = (int)fy;
        int iy0 = min(max(ify, 0), GH - 1);
        int iy1 = min(max(ify + 1, 0), GH - 1);
        const int yo0 = iy0 * (GW * C), yo1 = iy1 * (GW * C);

        float2 gv = *reinterpret_cast<const float2*>(
            guide + (size_t)n * HW + (size_t)row * W + x0);
        float gz2[2] = {gv.x, gv.y};

        unsigned long long acc[2][6];
        #pragma unroll
        for (int p = 0; p < 2; ++p)
            #pragma unroll
            for (int q = 0; q < 6; ++q) acc[p][q] = 0ULL;

        #pragma unroll
        for (int p = 0; p < 2; ++p) {
            // z weights from guide
            float tz = gz2[p] * 8.0f - 0.5f;
            float fz = floorf(tz);
            float bz = tz - fz;
            int ifz = (int)fz;
            int iz0 = min(max(ifz, 0), GD - 1);
            int iz1 = min(max(ifz + 1, 0), GD - 1);
            const int zo0 = iz0 * ZSTRIDE, zo1 = iz1 * ZSTRIDE;

            const float bx_p = bxa[p];

            #pragma unroll
            for (int dz = 0; dz < 2; ++dz) {
                const int zoff = dz ? zo1 : zo0;
                const float wz = dz ? bz : 1.0f - bz;
                #pragma unroll
                for (int dy = 0; dy < 2; ++dy) {
                    const int zyoff = zoff + (dy ? yo1 : yo0);
                    const float wzy = wz * (dy ? by : 1.0f - by);
                    #pragma unroll
                    for (int dx = 0; dx < 2; ++dx) {
                        const float w = wzy * (dx ? bx_p : 1.0f - bx_p);
                        const float* cp = s + zyoff + (dx ? xo1 : xo0);
                        unsigned long long wp = pack2(w);
                        const ulonglong2* q2 =
                            reinterpret_cast<const ulonglong2*>(cp);
                        ulonglong2 q0 = q2[0], q1 = q2[1], qq = q2[2];
                        acc[p][0] = fma2(wp, q0.x, acc[p][0]);
                        acc[p][1] = fma2(wp, q0.y, acc[p][1]);
                        acc[p][2] = fma2(wp, q1.x, acc[p][2]);
                        acc[p][3] = fma2(wp, q1.y, acc[p][3]);
                        acc[p][4] = fma2(wp, qq.x, acc[p][4]);
                        acc[p][5] = fma2(wp, qq.y, acc[p][5]);
                    }
                }
            }
        }

        // ---- Store: per channel, float2 across the 2 pixels ----
        float* ob_base = out + (size_t)n * C * HW + (size_t)row * W + x0;
        #pragma unroll
        for (int c2 = 0; c2 < 6; ++c2) {
            float2 lo, hi;
            lo.x = __uint_as_float((unsigned)acc[0][c2]);
            lo.y = __uint_as_float((unsigned)acc[1][c2]);
            hi.x = __uint_as_float((unsigned)(acc[0][c2] >> 32));
            hi.y = __uint_as_float((unsigned)(acc[1][c2] >> 32));
            float* ob = ob_base + (size_t)(2 * c2) * HW;
            *reinterpret_cast<float2*>(ob)      = lo;
            *reinterpret_cast<float2*>(ob + HW) = hi;
        }
    }
}

extern "C" void kernel_launch(void* const* d_in, const int* in_sizes, int n_in,
                              void* d_out, int out_size) {
    const float* grid  = (const float*)d_in[0];   // (4,12,8,16,16) f32
    const float* guide = (const float*)d_in[1];   // (4,1,1024,1024) f32
    float* out = (float*)d_out;                   // (4,12,1024,1024) f32

    const int smem_bytes = SMEM_FLOATS * sizeof(float);  // 98432
    cudaFuncSetAttribute(slice_kernel,
                         cudaFuncAttributeMaxDynamicSharedMemorySize,
                         smem_bytes);

    dim3 gridDim(H / ROWS_PER_BLOCK, Nb);  // (512, 4) = 2048 blocks
    slice_kernel<<<gridDim, THREADS, smem_bytes>>>(grid, guide, out);
}

// round 6
// speedup vs baseline: 4.6685x; 1.5595x over previous
#include <cuda_runtime.h>
#include <cuda_fp16.h>
#include <cstdint>

// Problem constants
static constexpr int Nb = 4, C = 12, GD = 8, GH = 16, GW = 16;
static constexpr int H = 1024, W = 1024;
static constexpr int HW = H * W;
static constexpr int GRID_PER_N = C * GD * GH * GW;   // 24576 floats

// Half-precision grid in smem, layout [z][y][x][c] packed (12 halfs = 24 B per
// (z,y,x) entry). Z-slab stride padded: 16*16*12 = 3072 halfs -> 3076 halfs
// (6152 B = 1538 words, 1538 mod 32 = 2): each z level shifts the bank pair by
// 2 words, so the 8 z levels of a warp hit 16 disjoint banks for LDS.64 -> no
// conflicts. 24-half tail pad covers the x-adjacency overread at (7,15,15).
static constexpr int ZSTRIDE_H  = GH * GW * C + 4;    // 3076 halfs
static constexpr int SMEM_HALFS = GD * ZSTRIDE_H + 24;
static constexpr int SMEM_BYTES = SMEM_HALFS * 2;     // 49264 B

static constexpr int THREADS = 512;                   // 1 px/thread, half a row
static constexpr int ROWS_PER_BLOCK = 4;

__device__ __forceinline__ __half2 u2h(unsigned u) {
    return *reinterpret_cast<__half2*>(&u);
}

// Fetch 48 B (both x-corners, 12 ch each) and x-lerp into 6 half2.
__device__ __forceinline__ void fetch_xlerp(const __half* sh, int off,
                                            __half2 wx0, __half2 wx1,
                                            __half2* r) {
    const uint2* p = reinterpret_cast<const uint2*>(sh + off);
    uint2 a0 = p[0], a1 = p[1], a2 = p[2];   // corner ix0: ch 0..11
    uint2 b0 = p[3], b1 = p[4], b2 = p[5];   // corner ix0+1: ch 0..11
    r[0] = __hfma2(u2h(b0.x), wx1, __hmul2(u2h(a0.x), wx0));
    r[1] = __hfma2(u2h(b0.y), wx1, __hmul2(u2h(a0.y), wx0));
    r[2] = __hfma2(u2h(b1.x), wx1, __hmul2(u2h(a1.x), wx0));
    r[3] = __hfma2(u2h(b1.y), wx1, __hmul2(u2h(a1.y), wx0));
    r[4] = __hfma2(u2h(b2.x), wx1, __hmul2(u2h(a2.x), wx0));
    r[5] = __hfma2(u2h(b2.y), wx1, __hmul2(u2h(a2.y), wx0));
}

__global__ __launch_bounds__(THREADS, 3)
void slice_kernel(const float* __restrict__ grid,
                  const float* __restrict__ guide,
                  float* __restrict__ out) {
    extern __shared__ __align__(16) __half sh[];

    const int n   = blockIdx.y;
    const int tid = threadIdx.x;

    // ---- Load grid[n] (c,z,y,x) f32 -> smem half (z, y, x, c) ----
    const float* g = grid + (size_t)n * GRID_PER_N;
    #pragma unroll
    for (int i = tid * 4; i < GRID_PER_N; i += THREADS * 4) {
        float4 v = *reinterpret_cast<const float4*>(g + i);
        int c   = i >> 11;        // / (GD*GH*GW)
        int zyx = i & 2047;       // z*256 + y*16 + x (x multiple of 4)
        int z   = zyx >> 8;
        int yx  = zyx & 255;
        int base = z * ZSTRIDE_H + yx * C + c;
        sh[base]         = __float2half_rn(v.x);
        sh[base + C]     = __float2half_rn(v.y);
        sh[base + 2 * C] = __float2half_rn(v.z);
        sh[base + 3 * C] = __float2half_rn(v.w);
    }
    __syncthreads();

    // Geometry: blockIdx.x = rowblock*2 + x-segment; 512 consecutive px.
    const int seg    = blockIdx.x & 1;
    const int rowblk = blockIdx.x >> 1;
    const int x      = seg * 512 + tid;

    // x cell + weights. Edge trick: fetch is always [ix, ix+1]; when the
    // reference clamps (ifx<0 or ifx>=15) both corners collapse onto ix, i.e.
    // total weight 1 on corner0 and 0 on the (junk) corner1.
    float tx = (x + 0.5f) * (1.0f / 64.0f) - 0.5f;
    float fx = floorf(tx);
    int  ifx = (int)fx;
    float bx = tx - fx;
    float w1f = (ifx < 0 || ifx >= GW - 1) ? 0.0f : bx;
    const __half2 wx0 = __float2half2_rn(1.0f - w1f);
    const __half2 wx1 = __float2half2_rn(w1f);
    const int xoff = min(max(ifx, 0), GW - 1) * C;   // halfs

    const float* gd = guide + (size_t)n * HW + x;
    float* ob = out + (size_t)n * C * HW + x;

    #pragma unroll 1
    for (int j = 0; j < ROWS_PER_BLOCK; ++j) {
        const int row = rowblk * ROWS_PER_BLOCK + j;

        // y weights (uniform across block)
        float ty = (row + 0.5f) * (16.0f / 1024.0f) - 0.5f;
        float fy = floorf(ty);
        float by = ty - fy;
        int ify = (int)fy;
        int iy0 = min(max(ify, 0), GH - 1);
        int iy1 = min(max(ify + 1, 0), GH - 1);
        const int yo0 = iy0 * (GW * C), yo1 = iy1 * (GW * C);
        const __half2 wy0 = __float2half2_rn(1.0f - by);
        const __half2 wy1 = __float2half2_rn(by);

        // z cell from guide (per pixel)
        float gz = gd[(size_t)row * W];
        float tz = gz * 8.0f - 0.5f;
        float fz = floorf(tz);
        float bz = tz - fz;
        int ifz = (int)fz;
        int iz0 = min(max(ifz, 0), GD - 1);
        int iz1 = min(max(ifz + 1, 0), GD - 1);
        const int zo0 = iz0 * ZSTRIDE_H, zo1 = iz1 * ZSTRIDE_H;
        const __half2 wz0 = __float2half2_rn(1.0f - bz);
        const __half2 wz1 = __float2half2_rn(bz);

        __half2 vy0[6], vy1[6];
        {
            __half2 a[6], b[6];
            fetch_xlerp(sh, zo0 + yo0 + xoff, wx0, wx1, a);
            fetch_xlerp(sh, zo0 + yo1 + xoff, wx0, wx1, b);
            #pragma unroll
            for (int k = 0; k < 6; ++k)
                vy0[k] = __hfma2(b[k], wy1, __hmul2(a[k], wy0));
            fetch_xlerp(sh, zo1 + yo0 + xoff, wx0, wx1, a);
            fetch_xlerp(sh, zo1 + yo1 + xoff, wx0, wx1, b);
            #pragma unroll
            for (int k = 0; k < 6; ++k)
                vy1[k] = __hfma2(b[k], wy1, __hmul2(a[k], wy0));
        }

        float* obr = ob + (size_t)row * W;
        #pragma unroll
        for (int k = 0; k < 6; ++k) {
            __half2 vz = __hfma2(vy1[k], wz1, __hmul2(vy0[k], wz0));
            float2 f = __half22float2(vz);
            obr[(size_t)(2 * k) * HW]     = f.x;
            obr[(size_t)(2 * k + 1) * HW] = f.y;
        }
    }
}

extern "C" void kernel_launch(void* const* d_in, const int* in_sizes, int n_in,
                              void* d_out, int out_size) {
    const float* grid  = (const float*)d_in[0];   // (4,12,8,16,16) f32
    const float* guide = (const float*)d_in[1];   // (4,1,1024,1024) f32
    float* out = (float*)d_out;                   // (4,12,1024,1024) f32

    cudaFuncSetAttribute(slice_kernel,
                         cudaFuncAttributeMaxDynamicSharedMemorySize,
                         SMEM_BYTES);

    dim3 gridDim((H / ROWS_PER_BLOCK) * 2, Nb);   // (512, 4) = 2048 blocks
    slice_kernel<<<gridDim, THREADS, SMEM_BYTES>>>(grid, guide, out);
}